// round 5
// baseline (speedup 1.0000x reference)
#include <cuda_runtime.h>
#include <cuda_bf16.h>
#include <math.h>

// ---------------- problem constants ----------------
#define BB   4
#define NN   256
#define DD   384
#define LL   12
#define F1C  1536
#define F2C  384
#define MM   8
#define HH   4
#define TT   260          // 4 skill tokens + 256
#define DH   96           // D / H
#define ROWS (BB*TT)      // 1040

#define GCNT   (LL*F1C*F2C)          // 7,077,888 groups per side
#define OUTROW (2LL*GCNT)

// ---------------- device scratch (static, no allocation) ----------------
#define OFF_TOK  0
#define SZ_TOK   (ROWS*DD)
#define OFF_Y    (OFF_TOK + SZ_TOK)
#define SZ_Y     (ROWS*DD)
#define OFF_Q    (OFF_Y + SZ_Y)
#define SZ_Q     (BB*HH*TT*DH)
#define OFF_KT   (OFF_Q + SZ_Q)
#define SZ_KT    (BB*HH*TT*DH)
#define OFF_V    (OFF_KT + SZ_KT)
#define SZ_V     (BB*HH*TT*DH)
#define OFF_SC   (OFF_V + SZ_V)
#define SZ_SC    (BB*HH*TT*TT)
#define OFF_O    (OFF_SC + SZ_SC)
#define SZ_O     (ROWS*DD)
#define OFF_FF   (OFF_O + SZ_O)
#define SZ_FF    (ROWS*2*DD)
#define OFF_W    (OFF_FF + SZ_FF)
#define SZ_W     32
#define SCRATCH_TOTAL (OFF_W + SZ_W)

__device__ float g_scratch[SCRATCH_TOTAL];

// quantized hard-concrete gates: 2*GCNT groups x 8 gates, u16 fixed point
__device__ unsigned short g_z16[(size_t)2 * GCNT * 8];

__device__ __forceinline__ float tanh_fast(float x)
{
    float r;
    asm("tanh.approx.f32 %0, %1;" : "=f"(r) : "f"(x));
    return r;
}

// ---------------- batched GEMM: 64x64 tile, 4x4/thread, smem double-buffered ----------------
// C = act(scale*(A@W) + bias [+R])
// epi: 0=none, 1=gelu(tanh), 2=+R[col], 3=+R residual, 4=qkv scatter
__global__ void __launch_bounds__(256) gemm_kernel(
    const float* __restrict__ A, const float* __restrict__ W,
    const float* __restrict__ bias, const float* __restrict__ R,
    float* __restrict__ C,
    int Mr, int N, int K,
    long long aBS, long long wBS, long long cBS1, long long cBS2, int cdiv,
    int ldc, float scale, int epi)
{
    int z = blockIdx.z;
    A += (size_t)z * aBS;
    W += (size_t)z * wBS;
    size_t coff = (size_t)(z / cdiv) * cBS1 + (size_t)(z % cdiv) * cBS2;
    C += coff;
    const float* Rm = (epi == 3) ? (R + coff) : R;

    __shared__ float As[2][16][64];
    __shared__ float Ws[2][16][64];

    int bm = blockIdx.y * 64, bn = blockIdx.x * 64;
    int tid = threadIdx.x;
    int tx = tid & 15, ty = tid >> 4;

    int la_m = tid & 63;            // row within tile
    int la_k = (tid >> 6) << 2;     // 0,4,8,12
    int lw_k = tid >> 4;            // 0..15
    int lw_n = (tid & 15) << 2;     // 0..60

    int arow = bm + la_m;
    bool a_ok = arow < Mr;
    const float* Aptr = A + (size_t)(a_ok ? arow : 0) * K;
    bool w_ok = (bn + lw_n) < N;
    const float* Wptr = W + bn + lw_n;

    float acc[4][4];
#pragma unroll
    for (int i = 0; i < 4; i++)
#pragma unroll
        for (int j = 0; j < 4; j++) acc[i][j] = 0.f;

    // prologue: first K-slab -> buf 0
    {
        float4 av = make_float4(0.f, 0.f, 0.f, 0.f);
        float4 wv = make_float4(0.f, 0.f, 0.f, 0.f);
        if (a_ok && la_k < K) av = *(const float4*)(Aptr + la_k);
        if (w_ok && lw_k < K) wv = *(const float4*)(Wptr + (size_t)lw_k * N);
        As[0][la_k + 0][la_m] = av.x;
        As[0][la_k + 1][la_m] = av.y;
        As[0][la_k + 2][la_m] = av.z;
        As[0][la_k + 3][la_m] = av.w;
        *(float4*)&Ws[0][lw_k][lw_n] = wv;
    }
    __syncthreads();

    int cur = 0;
    for (int k0 = 0; k0 < K; k0 += 16) {
        int kn = k0 + 16;
        float4 av = make_float4(0.f, 0.f, 0.f, 0.f);
        float4 wv = make_float4(0.f, 0.f, 0.f, 0.f);
        if (kn < K) {
            if (a_ok && (kn + la_k) < K) av = *(const float4*)(Aptr + kn + la_k);
            if (w_ok && (kn + lw_k) < K) wv = *(const float4*)(Wptr + (size_t)(kn + lw_k) * N);
        }

        // compute from buf[cur] with register pipelining over kk
        float4 a_c = *(const float4*)&As[cur][0][ty << 2];
        float4 w_c = *(const float4*)&Ws[cur][0][tx << 2];
#pragma unroll
        for (int kk = 0; kk < 16; kk++) {
            float4 a_n, w_n;
            if (kk < 15) {
                a_n = *(const float4*)&As[cur][kk + 1][ty << 2];
                w_n = *(const float4*)&Ws[cur][kk + 1][tx << 2];
            }
            acc[0][0] = fmaf(a_c.x, w_c.x, acc[0][0]);
            acc[0][1] = fmaf(a_c.x, w_c.y, acc[0][1]);
            acc[0][2] = fmaf(a_c.x, w_c.z, acc[0][2]);
            acc[0][3] = fmaf(a_c.x, w_c.w, acc[0][3]);
            acc[1][0] = fmaf(a_c.y, w_c.x, acc[1][0]);
            acc[1][1] = fmaf(a_c.y, w_c.y, acc[1][1]);
            acc[1][2] = fmaf(a_c.y, w_c.z, acc[1][2]);
            acc[1][3] = fmaf(a_c.y, w_c.w, acc[1][3]);
            acc[2][0] = fmaf(a_c.z, w_c.x, acc[2][0]);
            acc[2][1] = fmaf(a_c.z, w_c.y, acc[2][1]);
            acc[2][2] = fmaf(a_c.z, w_c.z, acc[2][2]);
            acc[2][3] = fmaf(a_c.z, w_c.w, acc[2][3]);
            acc[3][0] = fmaf(a_c.w, w_c.x, acc[3][0]);
            acc[3][1] = fmaf(a_c.w, w_c.y, acc[3][1]);
            acc[3][2] = fmaf(a_c.w, w_c.z, acc[3][2]);
            acc[3][3] = fmaf(a_c.w, w_c.w, acc[3][3]);
            if (kk < 15) { a_c = a_n; w_c = w_n; }
        }

        // stage next slab into the other buffer (no reader conflict)
        if (kn < K) {
            int nxt = cur ^ 1;
            As[nxt][la_k + 0][la_m] = av.x;
            As[nxt][la_k + 1][la_m] = av.y;
            As[nxt][la_k + 2][la_m] = av.z;
            As[nxt][la_k + 3][la_m] = av.w;
            *(float4*)&Ws[nxt][lw_k][lw_n] = wv;
        }
        __syncthreads();
        cur ^= 1;
    }

    int colb = bn + (tx << 2);
    if (colb >= N) return;
    float4 bv = make_float4(0.f, 0.f, 0.f, 0.f);
    if (bias) bv = *(const float4*)(bias + colb);
    float4 ev = make_float4(0.f, 0.f, 0.f, 0.f);
    if (epi == 2) ev = *(const float4*)(R + colb);

    float* qb_  = C;
    float* kTb_ = C + SZ_Q;
    float* vb_  = C + 2 * SZ_Q;

#pragma unroll
    for (int i = 0; i < 4; i++) {
        int row = bm + (ty << 2) + i;
        if (row >= Mr) continue;
        float4 r;
        r.x = acc[i][0] * scale + bv.x;
        r.y = acc[i][1] * scale + bv.y;
        r.z = acc[i][2] * scale + bv.z;
        r.w = acc[i][3] * scale + bv.w;
        if (epi == 1) {
            float v;
            v = r.x; r.x = 0.5f * v * (1.f + tanh_fast(0.7978845608028654f * (v + 0.044715f * v * v * v)));
            v = r.y; r.y = 0.5f * v * (1.f + tanh_fast(0.7978845608028654f * (v + 0.044715f * v * v * v)));
            v = r.z; r.z = 0.5f * v * (1.f + tanh_fast(0.7978845608028654f * (v + 0.044715f * v * v * v)));
            v = r.w; r.w = 0.5f * v * (1.f + tanh_fast(0.7978845608028654f * (v + 0.044715f * v * v * v)));
        } else if (epi == 2) {
            r.x += ev.x; r.y += ev.y; r.z += ev.z; r.w += ev.w;
        } else if (epi == 3) {
            float4 rv = *(const float4*)(Rm + (size_t)row * ldc + colb);
            r.x += rv.x; r.y += rv.y; r.z += rv.z; r.w += rv.w;
        }
        if (epi == 4) {
            int b = row / TT, t = row - b * TT;
            float rv[4] = {r.x, r.y, r.z, r.w};
#pragma unroll
            for (int j = 0; j < 4; j++) {
                int c = colb + j;
                int s = c / DD;
                int rem = c - s * DD;
                int h = rem / DH;
                int d = rem - h * DH;
                int bh = b * HH + h;
                if (s == 0)      qb_ [((size_t)bh * TT + t) * DH + d] = rv[j];
                else if (s == 1) kTb_[((size_t)bh * DH + d) * TT + t] = rv[j];
                else             vb_ [((size_t)bh * TT + t) * DH + d] = rv[j];
            }
        } else {
            *(float4*)(C + (size_t)row * ldc + colb) = r;
        }
    }
}

// ---------------- fill skill tokens ----------------
__global__ void fill_skills_kernel(const float* __restrict__ skills, float* __restrict__ tok)
{
    int i = blockIdx.x * 256 + threadIdx.x;
    if (i >= BB * 4 * DD) return;
    int b = i / (4 * DD);
    int r = i % (4 * DD);
    tok[(size_t)(b * TT) * DD + r] = skills[r];
}

// ---------------- layernorm ----------------
__global__ void __launch_bounds__(128) ln_kernel(
    const float* __restrict__ X, const float* __restrict__ gw,
    const float* __restrict__ bw, float* __restrict__ Y)
{
    int row = blockIdx.x;
    int tid = threadIdx.x;
    const float* x = X + (size_t)row * DD;
    float v0 = x[tid], v1 = x[tid + 128], v2 = x[tid + 256];
    float s = v0 + v1 + v2;
    float q = v0 * v0 + v1 * v1 + v2 * v2;
#pragma unroll
    for (int o = 16; o; o >>= 1) {
        s += __shfl_xor_sync(0xffffffffu, s, o);
        q += __shfl_xor_sync(0xffffffffu, q, o);
    }
    __shared__ float ss[4], qq[4];
    if ((tid & 31) == 0) { ss[tid >> 5] = s; qq[tid >> 5] = q; }
    __syncthreads();
    s = ss[0] + ss[1] + ss[2] + ss[3];
    q = qq[0] + qq[1] + qq[2] + qq[3];
    float mean = s * (1.f / DD);
    float var = q * (1.f / DD) - mean * mean;
    float inv = rsqrtf(var + 1e-6f);
    float* y = Y + (size_t)row * DD;
    y[tid]       = (v0 - mean) * inv * gw[tid]       + bw[tid];
    y[tid + 128] = (v1 - mean) * inv * gw[tid + 128] + bw[tid + 128];
    y[tid + 256] = (v2 - mean) * inv * gw[tid + 256] + bw[tid + 256];
}

// ---------------- softmax over 260 cols ----------------
__global__ void __launch_bounds__(128) softmax260_kernel(float* __restrict__ S)
{
    int row = blockIdx.x;
    float* p = S + (size_t)row * TT;
    int tid = threadIdx.x;
    float v0 = p[tid], v1 = p[tid + 128];
    float v2 = (tid < 4) ? p[tid + 256] : -1e30f;
    float mx = fmaxf(fmaxf(v0, v1), v2);
#pragma unroll
    for (int o = 16; o; o >>= 1) mx = fmaxf(mx, __shfl_xor_sync(0xffffffffu, mx, o));
    __shared__ float sm[4];
    if ((tid & 31) == 0) sm[tid >> 5] = mx;
    __syncthreads();
    mx = fmaxf(fmaxf(sm[0], sm[1]), fmaxf(sm[2], sm[3]));
    float e0 = __expf(v0 - mx), e1 = __expf(v1 - mx);
    float e2 = (tid < 4) ? __expf(v2 - mx) : 0.f;
    float s = e0 + e1 + e2;
#pragma unroll
    for (int o = 16; o; o >>= 1) s += __shfl_xor_sync(0xffffffffu, s, o);
    __shared__ float sq[4];
    if ((tid & 31) == 0) sq[tid >> 5] = s;
    __syncthreads();
    s = sq[0] + sq[1] + sq[2] + sq[3];
    float inv = __fdividef(1.f, s);
    p[tid] = e0 * inv;
    p[tid + 128] = e1 * inv;
    if (tid < 4) p[tid + 256] = e2 * inv;
}

// ---------------- w = softmax(mean(tok[:, :4]) @ mk^T / sqrt(D)) ----------------
__global__ void __launch_bounds__(256) compute_w_kernel(
    const float* __restrict__ tok, const float* __restrict__ mk,
    float* __restrict__ wout)
{
    int tid = threadIdx.x;
    int p = tid >> 3;
    int b = p >> 3, m = p & 7;
    int j = tid & 7;
    const float* tb = tok + (size_t)b * TT * DD;
    const float* key = mk + (size_t)m * DD;
    float acc = 0.f;
    for (int d = j * 4; d < DD; d += 32) {
        float4 k4 = *(const float4*)(key + d);
        float4 t0 = *(const float4*)(tb + d);
        float4 t1 = *(const float4*)(tb + DD + d);
        float4 t2 = *(const float4*)(tb + 2 * DD + d);
        float4 t3 = *(const float4*)(tb + 3 * DD + d);
        acc = fmaf(0.25f * (t0.x + t1.x + t2.x + t3.x), k4.x, acc);
        acc = fmaf(0.25f * (t0.y + t1.y + t2.y + t3.y), k4.y, acc);
        acc = fmaf(0.25f * (t0.z + t1.z + t2.z + t3.z), k4.z, acc);
        acc = fmaf(0.25f * (t0.w + t1.w + t2.w + t3.w), k4.w, acc);
    }
    acc += __shfl_xor_sync(0xffffffffu, acc, 4);
    acc += __shfl_xor_sync(0xffffffffu, acc, 2);
    acc += __shfl_xor_sync(0xffffffffu, acc, 1);
    __shared__ float sl[32];
    if (j == 0) sl[p] = acc * 0.05103103630798288f;
    __syncthreads();
    if (tid < 32) {
        float logit = sl[tid];
        float mx = logit;
#pragma unroll
        for (int o = 4; o; o >>= 1) mx = fmaxf(mx, __shfl_xor_sync(0xffffffffu, mx, o));
        float e = __expf(logit - mx);
        float s = e;
#pragma unroll
        for (int o = 4; o; o >>= 1) s += __shfl_xor_sync(0xffffffffu, s, o);
        wout[tid] = e / s;
    }
}

// ---------------- hard-concrete via HW tanh: z = clamp(0.5 + 0.6*tanh(0.75*t)) ----------------
__device__ __forceinline__ float hc_z(float u, float la)
{
    u = fminf(fmaxf(u, 1e-6f), 1.0f - 1e-6f);
    float t = (__logf(u) - __logf(1.0f - u) + la) * 0.75f;
    float z = fmaf(0.6f, tanh_fast(t), 0.5f);
    return fminf(fmaxf(z, 0.0f), 1.0f);
}

__device__ __forceinline__ unsigned int qpack2(float z0, float z1)
{
    unsigned int q0 = __float2uint_rn(z0 * 65535.f);
    unsigned int q1 = __float2uint_rn(z1 * 65535.f);
    return q0 | (q1 << 16);
}

// ---- stage 1: persistent z-stage; 2 CTAs/SM, grid-stride; co-runs with GEMM chain ----
__global__ void __launch_bounds__(256) zstage_kernel(
    const float* __restrict__ u_a, const float* __restrict__ la_a,
    const float* __restrict__ u_b, const float* __restrict__ la_b)
{
    const size_t stride = (size_t)gridDim.x * 256;
    for (size_t g = (size_t)blockIdx.x * 256 + threadIdx.x;
         g < (size_t)2 * GCNT; g += stride) {
        bool isB = g >= (size_t)GCNT;
        size_t gg = isB ? g - GCNT : g;
        const float* up = isB ? u_b : u_a;
        const float* lp = isB ? la_b : la_a;

        size_t e8 = gg * 8;
        float4 u0 = __ldcs((const float4*)(up + e8));
        float4 u1 = __ldcs((const float4*)(up + e8 + 4));
        float4 l0 = __ldcs((const float4*)(lp + e8));
        float4 l1 = __ldcs((const float4*)(lp + e8 + 4));

        uint4 packed;
        packed.x = qpack2(hc_z(u0.x, l0.x), hc_z(u0.y, l0.y));
        packed.y = qpack2(hc_z(u0.z, l0.z), hc_z(u0.w, l0.w));
        packed.z = qpack2(hc_z(u1.x, l1.x), hc_z(u1.y, l1.y));
        packed.w = qpack2(hc_z(u1.z, l1.z), hc_z(u1.w, l1.w));

        __stcs((uint4*)(g_z16 + g * 8), packed);
    }
}

// ---- stage 2: out[b, g] = (sum_m z16[g,m] * w'[b,m]) * phi[g] ----
__global__ void __launch_bounds__(256) delta_final_kernel(
    const float* __restrict__ phi_a, const float* __restrict__ phi_b,
    const float* __restrict__ wbuf, float* __restrict__ out)
{
    __shared__ float ws[32];
    if (threadIdx.x < 32) ws[threadIdx.x] = wbuf[threadIdx.x] * (1.0f / 65535.0f);
    __syncthreads();

    size_t g = (size_t)blockIdx.x * 256 + threadIdx.x;
    bool isB = g >= (size_t)GCNT;
    size_t gg = isB ? g - GCNT : g;
    const float* pp = isB ? phi_b : phi_a;

    uint4 zz = __ldcs((const uint4*)(g_z16 + g * 8));
    float z[8];
    z[0] = (float)(zz.x & 0xFFFFu); z[1] = (float)(zz.x >> 16);
    z[2] = (float)(zz.y & 0xFFFFu); z[3] = (float)(zz.y >> 16);
    z[4] = (float)(zz.z & 0xFFFFu); z[5] = (float)(zz.z >> 16);
    z[6] = (float)(zz.w & 0xFFFFu); z[7] = (float)(zz.w >> 16);

    float phi = __ldcs(pp + gg);

    size_t base = (isB ? (size_t)GCNT : 0) + gg;
#pragma unroll
    for (int b = 0; b < 4; b++) {
        float acc = 0.f;
#pragma unroll
        for (int m = 0; m < 8; m++) acc = fmaf(z[m], ws[b * 8 + m], acc);
        __stcs(out + (size_t)b * OUTROW + base, acc * phi);
    }
}

// ---------------- host launch ----------------
extern "C" void kernel_launch(void* const* d_in, const int* in_sizes, int n_in,
                              void* d_out, int out_size)
{
    const float* x      = (const float*)d_in[0];
    const float* u_a    = (const float*)d_in[1];
    const float* u_b    = (const float*)d_in[2];
    const float* phi_a  = (const float*)d_in[3];
    const float* phi_b  = (const float*)d_in[4];
    const float* la_a   = (const float*)d_in[5];
    const float* la_b   = (const float*)d_in[6];
    const float* Wp     = (const float*)d_in[7];
    const float* bp     = (const float*)d_in[8];
    const float* skills = (const float*)d_in[9];
    const float* cenc   = (const float*)d_in[10];
    const float* ln1_g  = (const float*)d_in[11];
    const float* ln1_b  = (const float*)d_in[12];
    const float* Wqkv   = (const float*)d_in[13];
    const float* bqkv   = (const float*)d_in[14];
    const float* Wo     = (const float*)d_in[15];
    const float* bo     = (const float*)d_in[16];
    const float* ln2_g  = (const float*)d_in[17];
    const float* ln2_b  = (const float*)d_in[18];
    const float* W1     = (const float*)d_in[19];
    const float* b1     = (const float*)d_in[20];
    const float* W2     = (const float*)d_in[21];
    const float* b2     = (const float*)d_in[22];
    const float* mk     = (const float*)d_in[23];
    float* out = (float*)d_out;

    float* scratch = nullptr;
    cudaGetSymbolAddress((void**)&scratch, g_scratch);
    float* tok  = scratch + OFF_TOK;
    float* ybuf = scratch + OFF_Y;
    float* qb   = scratch + OFF_Q;
    float* sc   = scratch + OFF_SC;
    float* ob   = scratch + OFF_O;
    float* ff   = scratch + OFF_FF;
    float* wbuf = scratch + OFF_W;
    float* kT   = scratch + OFF_KT;
    float* vb   = scratch + OFF_V;

    // one-time side-stream/event setup (host objects only)
    static cudaStream_t s_side = nullptr;
    static cudaEvent_t s_fork = nullptr, s_join = nullptr;
    if (!s_side) {
        int lo = 0, hi = 0;
        cudaDeviceGetStreamPriorityRange(&lo, &hi);   // lo = lowest priority (largest number)
        cudaStreamCreateWithPriority(&s_side, cudaStreamNonBlocking, lo);
        cudaEventCreateWithFlags(&s_fork, cudaEventDisableTiming);
        cudaEventCreateWithFlags(&s_join, cudaEventDisableTiming);
    }

    // ---- fork: persistent z-stage (2 CTAs/SM) co-runs with the chain ----
    cudaEventRecord(s_fork, 0);
    cudaStreamWaitEvent(s_side, s_fork, 0);
    zstage_kernel<<<296, 256, 0, s_side>>>(u_a, la_a, u_b, la_b);
    cudaEventRecord(s_join, s_side);

    // ---- transformer chain on main stream ----
    // 1. h = x@Wp + bp + count_enc
    gemm_kernel<<<dim3(DD / 64, NN / 64, BB), 256>>>(
        x, Wp, bp, cenc, tok + 4 * DD,
        NN, DD, DD,
        (long long)NN * DD, 0LL, (long long)TT * DD, 0LL, 1,
        DD, 1.0f, 2);

    // 2. skill tokens
    fill_skills_kernel<<<(BB * 4 * DD + 255) / 256, 256>>>(skills, tok);

    // 3. LN1
    ln_kernel<<<ROWS, 128>>>(tok, ln1_g, ln1_b, ybuf);

    // 4. qkv = y @ Wqkv + bqkv, scattered to q / kT / v
    gemm_kernel<<<dim3(3 * DD / 64, (ROWS + 63) / 64, 1), 256>>>(
        ybuf, Wqkv, bqkv, nullptr, qb,
        ROWS, 3 * DD, DD,
        0LL, 0LL, 0LL, 0LL, 1,
        0, 1.0f, 4);

    // 5. scores = q @ kT / sqrt(96)
    gemm_kernel<<<dim3((TT + 63) / 64, (TT + 63) / 64, BB * HH), 256>>>(
        qb, kT, nullptr, nullptr, sc,
        TT, TT, DH,
        (long long)TT * DH, (long long)TT * DH, (long long)TT * TT, 0LL, 1,
        TT, 0.10206207261596577f, 0);

    // 6. softmax
    softmax260_kernel<<<BB * HH * TT, 128>>>(sc);

    // 7. o = att @ v -> (B,T,D)
    gemm_kernel<<<dim3((DH + 63) / 64, (TT + 63) / 64, BB * HH), 256>>>(
        sc, vb, nullptr, nullptr, ob,
        TT, DH, TT,
        (long long)TT * TT, (long long)TT * DH,
        (long long)TT * DD, (long long)DH, HH,
        DD, 1.0f, 0);

    // 8. tok += o @ Wo + bo
    gemm_kernel<<<dim3(DD / 64, (ROWS + 63) / 64, 1), 256>>>(
        ob, Wo, bo, tok, tok,
        ROWS, DD, DD,
        0LL, 0LL, 0LL, 0LL, 1,
        DD, 1.0f, 3);

    // 9. LN2
    ln_kernel<<<ROWS, 128>>>(tok, ln2_g, ln2_b, ybuf);

    // 10. ff = gelu(y @ W1 + b1)
    gemm_kernel<<<dim3(2 * DD / 64, (ROWS + 63) / 64, 1), 256>>>(
        ybuf, W1, b1, nullptr, ff,
        ROWS, 2 * DD, DD,
        0LL, 0LL, 0LL, 0LL, 1,
        2 * DD, 1.0f, 1);

    // 11. tok += ff @ W2 + b2
    gemm_kernel<<<dim3(DD / 64, (ROWS + 63) / 64, 1), 256>>>(
        ff, W2, b2, tok, tok,
        ROWS, DD, 2 * DD,
        0LL, 0LL, 0LL, 0LL, 1,
        DD, 1.0f, 3);

    // 12. w
    compute_w_kernel<<<1, 256>>>(tok, mk, wbuf);

    // ---- join: final delta needs both w and z16 ----
    cudaStreamWaitEvent(0, s_join, 0);
    delta_final_kernel<<<(2 * GCNT) / 256, 256>>>(phi_a, phi_b, wbuf, out);
}

// round 6
// speedup vs baseline: 1.3929x; 1.3929x over previous
#include <cuda_runtime.h>
#include <cuda_bf16.h>
#include <math.h>

// ---------------- problem constants ----------------
#define BB   4
#define NN   256
#define DD   384
#define LL   12
#define F1C  1536
#define F2C  384
#define MM   8
#define HH   4
#define TT   260          // 4 skill tokens + 256
#define DH   96           // D / H
#define ROWS (BB*TT)      // 1040

#define GCNT   (LL*F1C*F2C)          // 7,077,888 groups per side
#define OUTROW (2LL*GCNT)

// ---------------- device scratch (static, no allocation) ----------------
#define OFF_TOK  0
#define SZ_TOK   (ROWS*DD)
#define OFF_Y    (OFF_TOK + SZ_TOK)
#define SZ_Y     (ROWS*DD)
#define OFF_Q    (OFF_Y + SZ_Y)
#define SZ_Q     (BB*HH*TT*DH)
#define OFF_KT   (OFF_Q + SZ_Q)
#define SZ_KT    (BB*HH*TT*DH)
#define OFF_V    (OFF_KT + SZ_KT)
#define SZ_V     (BB*HH*TT*DH)
#define OFF_SC   (OFF_V + SZ_V)
#define SZ_SC    (BB*HH*TT*TT)
#define OFF_O    (OFF_SC + SZ_SC)
#define SZ_O     (ROWS*DD)
#define OFF_FF   (OFF_O + SZ_O)
#define SZ_FF    (ROWS*2*DD)
#define OFF_W    (OFF_FF + SZ_FF)
#define SZ_W     32
#define SCRATCH_TOTAL (OFF_W + SZ_W)

__device__ float g_scratch[SCRATCH_TOTAL];

__device__ __forceinline__ float tanh_fast(float x)
{
    float r;
    asm("tanh.approx.f32 %0, %1;" : "=f"(r) : "f"(x));
    return r;
}

// ---------------- batched GEMM: 64x64 tile, 4x4/thread, smem double-buffered ----------------
// C = act(scale*(A@W) + bias [+R])
// A: (Mr x K) row-major. W: (K x N) row-major. C: ldc row stride.
// batch z: A += z*aBS, W += z*wBS, C += (z/cdiv)*cBS1 + (z%cdiv)*cBS2
// epi: 0=none, 1=gelu(tanh), 2=+R[col], 3=+R residual, 4=qkv scatter
__global__ void __launch_bounds__(256) gemm_kernel(
    const float* __restrict__ A, const float* __restrict__ W,
    const float* __restrict__ bias, const float* __restrict__ R,
    float* __restrict__ C,
    int Mr, int N, int K,
    long long aBS, long long wBS, long long cBS1, long long cBS2, int cdiv,
    int ldc, float scale, int epi)
{
    int z = blockIdx.z;
    A += (size_t)z * aBS;
    W += (size_t)z * wBS;
    size_t coff = (size_t)(z / cdiv) * cBS1 + (size_t)(z % cdiv) * cBS2;
    C += coff;
    const float* Rm = (epi == 3) ? (R + coff) : R;

    __shared__ float As[2][16][64];
    __shared__ float Ws[2][16][64];

    int bm = blockIdx.y * 64, bn = blockIdx.x * 64;
    int tid = threadIdx.x;
    int tx = tid & 15, ty = tid >> 4;

    int la_m = tid & 63;            // row within tile
    int la_k = (tid >> 6) << 2;     // 0,4,8,12
    int lw_k = tid >> 4;            // 0..15
    int lw_n = (tid & 15) << 2;     // 0..60

    int arow = bm + la_m;
    bool a_ok = arow < Mr;
    const float* Aptr = A + (size_t)(a_ok ? arow : 0) * K;
    bool w_ok = (bn + lw_n) < N;
    const float* Wptr = W + bn + lw_n;

    float acc[4][4];
#pragma unroll
    for (int i = 0; i < 4; i++)
#pragma unroll
        for (int j = 0; j < 4; j++) acc[i][j] = 0.f;

    // prologue: first K-slab -> buf 0
    {
        float4 av = make_float4(0.f, 0.f, 0.f, 0.f);
        float4 wv = make_float4(0.f, 0.f, 0.f, 0.f);
        if (a_ok && la_k < K) av = *(const float4*)(Aptr + la_k);
        if (w_ok && lw_k < K) wv = *(const float4*)(Wptr + (size_t)lw_k * N);
        As[0][la_k + 0][la_m] = av.x;
        As[0][la_k + 1][la_m] = av.y;
        As[0][la_k + 2][la_m] = av.z;
        As[0][la_k + 3][la_m] = av.w;
        *(float4*)&Ws[0][lw_k][lw_n] = wv;
    }
    __syncthreads();

    int cur = 0;
    for (int k0 = 0; k0 < K; k0 += 16) {
        int kn = k0 + 16;
        float4 av = make_float4(0.f, 0.f, 0.f, 0.f);
        float4 wv = make_float4(0.f, 0.f, 0.f, 0.f);
        if (kn < K) {
            if (a_ok && (kn + la_k) < K) av = *(const float4*)(Aptr + kn + la_k);
            if (w_ok && (kn + lw_k) < K) wv = *(const float4*)(Wptr + (size_t)(kn + lw_k) * N);
        }

        // compute from buf[cur] with register pipelining over kk
        float4 a_c = *(const float4*)&As[cur][0][ty << 2];
        float4 w_c = *(const float4*)&Ws[cur][0][tx << 2];
#pragma unroll
        for (int kk = 0; kk < 16; kk++) {
            float4 a_n, w_n;
            if (kk < 15) {
                a_n = *(const float4*)&As[cur][kk + 1][ty << 2];
                w_n = *(const float4*)&Ws[cur][kk + 1][tx << 2];
            }
            acc[0][0] = fmaf(a_c.x, w_c.x, acc[0][0]);
            acc[0][1] = fmaf(a_c.x, w_c.y, acc[0][1]);
            acc[0][2] = fmaf(a_c.x, w_c.z, acc[0][2]);
            acc[0][3] = fmaf(a_c.x, w_c.w, acc[0][3]);
            acc[1][0] = fmaf(a_c.y, w_c.x, acc[1][0]);
            acc[1][1] = fmaf(a_c.y, w_c.y, acc[1][1]);
            acc[1][2] = fmaf(a_c.y, w_c.z, acc[1][2]);
            acc[1][3] = fmaf(a_c.y, w_c.w, acc[1][3]);
            acc[2][0] = fmaf(a_c.z, w_c.x, acc[2][0]);
            acc[2][1] = fmaf(a_c.z, w_c.y, acc[2][1]);
            acc[2][2] = fmaf(a_c.z, w_c.z, acc[2][2]);
            acc[2][3] = fmaf(a_c.z, w_c.w, acc[2][3]);
            acc[3][0] = fmaf(a_c.w, w_c.x, acc[3][0]);
            acc[3][1] = fmaf(a_c.w, w_c.y, acc[3][1]);
            acc[3][2] = fmaf(a_c.w, w_c.z, acc[3][2]);
            acc[3][3] = fmaf(a_c.w, w_c.w, acc[3][3]);
            if (kk < 15) { a_c = a_n; w_c = w_n; }
        }

        // stage next slab into the other buffer
        if (kn < K) {
            int nxt = cur ^ 1;
            As[nxt][la_k + 0][la_m] = av.x;
            As[nxt][la_k + 1][la_m] = av.y;
            As[nxt][la_k + 2][la_m] = av.z;
            As[nxt][la_k + 3][la_m] = av.w;
            *(float4*)&Ws[nxt][lw_k][lw_n] = wv;
        }
        __syncthreads();
        cur ^= 1;
    }

    int colb = bn + (tx << 2);
    if (colb >= N) return;
    float4 bv = make_float4(0.f, 0.f, 0.f, 0.f);
    if (bias) bv = *(const float4*)(bias + colb);
    float4 ev = make_float4(0.f, 0.f, 0.f, 0.f);
    if (epi == 2) ev = *(const float4*)(R + colb);

    float* qb_  = C;
    float* kTb_ = C + SZ_Q;
    float* vb_  = C + 2 * SZ_Q;

#pragma unroll
    for (int i = 0; i < 4; i++) {
        int row = bm + (ty << 2) + i;
        if (row >= Mr) continue;
        float4 r;
        r.x = acc[i][0] * scale + bv.x;
        r.y = acc[i][1] * scale + bv.y;
        r.z = acc[i][2] * scale + bv.z;
        r.w = acc[i][3] * scale + bv.w;
        if (epi == 1) {
            float v;
            v = r.x; r.x = 0.5f * v * (1.f + tanh_fast(0.7978845608028654f * (v + 0.044715f * v * v * v)));
            v = r.y; r.y = 0.5f * v * (1.f + tanh_fast(0.7978845608028654f * (v + 0.044715f * v * v * v)));
            v = r.z; r.z = 0.5f * v * (1.f + tanh_fast(0.7978845608028654f * (v + 0.044715f * v * v * v)));
            v = r.w; r.w = 0.5f * v * (1.f + tanh_fast(0.7978845608028654f * (v + 0.044715f * v * v * v)));
        } else if (epi == 2) {
            r.x += ev.x; r.y += ev.y; r.z += ev.z; r.w += ev.w;
        } else if (epi == 3) {
            float4 rv = *(const float4*)(Rm + (size_t)row * ldc + colb);
            r.x += rv.x; r.y += rv.y; r.z += rv.z; r.w += rv.w;
        }
        if (epi == 4) {
            int b = row / TT, t = row - b * TT;
            float rv[4] = {r.x, r.y, r.z, r.w};
#pragma unroll
            for (int j = 0; j < 4; j++) {
                int c = colb + j;
                int s = c / DD;
                int rem = c - s * DD;
                int h = rem / DH;
                int d = rem - h * DH;
                int bh = b * HH + h;
                if (s == 0)      qb_ [((size_t)bh * TT + t) * DH + d] = rv[j];
                else if (s == 1) kTb_[((size_t)bh * DH + d) * TT + t] = rv[j];
                else             vb_ [((size_t)bh * TT + t) * DH + d] = rv[j];
            }
        } else {
            *(float4*)(C + (size_t)row * ldc + colb) = r;
        }
    }
}

// ---------------- fill skill tokens ----------------
__global__ void fill_skills_kernel(const float* __restrict__ skills, float* __restrict__ tok)
{
    int i = blockIdx.x * 256 + threadIdx.x;
    if (i >= BB * 4 * DD) return;
    int b = i / (4 * DD);
    int r = i % (4 * DD);
    tok[(size_t)(b * TT) * DD + r] = skills[r];
}

// ---------------- layernorm ----------------
__global__ void __launch_bounds__(128) ln_kernel(
    const float* __restrict__ X, const float* __restrict__ gw,
    const float* __restrict__ bw, float* __restrict__ Y)
{
    int row = blockIdx.x;
    int tid = threadIdx.x;
    const float* x = X + (size_t)row * DD;
    float v0 = x[tid], v1 = x[tid + 128], v2 = x[tid + 256];
    float s = v0 + v1 + v2;
    float q = v0 * v0 + v1 * v1 + v2 * v2;
#pragma unroll
    for (int o = 16; o; o >>= 1) {
        s += __shfl_xor_sync(0xffffffffu, s, o);
        q += __shfl_xor_sync(0xffffffffu, q, o);
    }
    __shared__ float ss[4], qq[4];
    if ((tid & 31) == 0) { ss[tid >> 5] = s; qq[tid >> 5] = q; }
    __syncthreads();
    s = ss[0] + ss[1] + ss[2] + ss[3];
    q = qq[0] + qq[1] + qq[2] + qq[3];
    float mean = s * (1.f / DD);
    float var = q * (1.f / DD) - mean * mean;
    float inv = rsqrtf(var + 1e-6f);
    float* y = Y + (size_t)row * DD;
    y[tid]       = (v0 - mean) * inv * gw[tid]       + bw[tid];
    y[tid + 128] = (v1 - mean) * inv * gw[tid + 128] + bw[tid + 128];
    y[tid + 256] = (v2 - mean) * inv * gw[tid + 256] + bw[tid + 256];
}

// ---------------- softmax over 260 cols ----------------
__global__ void __launch_bounds__(128) softmax260_kernel(float* __restrict__ S)
{
    int row = blockIdx.x;
    float* p = S + (size_t)row * TT;
    int tid = threadIdx.x;
    float v0 = p[tid], v1 = p[tid + 128];
    float v2 = (tid < 4) ? p[tid + 256] : -1e30f;
    float mx = fmaxf(fmaxf(v0, v1), v2);
#pragma unroll
    for (int o = 16; o; o >>= 1) mx = fmaxf(mx, __shfl_xor_sync(0xffffffffu, mx, o));
    __shared__ float sm[4];
    if ((tid & 31) == 0) sm[tid >> 5] = mx;
    __syncthreads();
    mx = fmaxf(fmaxf(sm[0], sm[1]), fmaxf(sm[2], sm[3]));
    float e0 = __expf(v0 - mx), e1 = __expf(v1 - mx);
    float e2 = (tid < 4) ? __expf(v2 - mx) : 0.f;
    float s = e0 + e1 + e2;
#pragma unroll
    for (int o = 16; o; o >>= 1) s += __shfl_xor_sync(0xffffffffu, s, o);
    __shared__ float sq[4];
    if ((tid & 31) == 0) sq[tid >> 5] = s;
    __syncthreads();
    s = sq[0] + sq[1] + sq[2] + sq[3];
    float inv = __fdividef(1.f, s);
    p[tid] = e0 * inv;
    p[tid + 128] = e1 * inv;
    if (tid < 4) p[tid + 256] = e2 * inv;
}

// ---------------- w = softmax(mean(tok[:, :4]) @ mk^T / sqrt(D)) ----------------
__global__ void __launch_bounds__(256) compute_w_kernel(
    const float* __restrict__ tok, const float* __restrict__ mk,
    float* __restrict__ wout)
{
    int tid = threadIdx.x;
    int p = tid >> 3;
    int b = p >> 3, m = p & 7;
    int j = tid & 7;
    const float* tb = tok + (size_t)b * TT * DD;
    const float* key = mk + (size_t)m * DD;
    float acc = 0.f;
    for (int d = j * 4; d < DD; d += 32) {
        float4 k4 = *(const float4*)(key + d);
        float4 t0 = *(const float4*)(tb + d);
        float4 t1 = *(const float4*)(tb + DD + d);
        float4 t2 = *(const float4*)(tb + 2 * DD + d);
        float4 t3 = *(const float4*)(tb + 3 * DD + d);
        acc = fmaf(0.25f * (t0.x + t1.x + t2.x + t3.x), k4.x, acc);
        acc = fmaf(0.25f * (t0.y + t1.y + t2.y + t3.y), k4.y, acc);
        acc = fmaf(0.25f * (t0.z + t1.z + t2.z + t3.z), k4.z, acc);
        acc = fmaf(0.25f * (t0.w + t1.w + t2.w + t3.w), k4.w, acc);
    }
    acc += __shfl_xor_sync(0xffffffffu, acc, 4);
    acc += __shfl_xor_sync(0xffffffffu, acc, 2);
    acc += __shfl_xor_sync(0xffffffffu, acc, 1);
    __shared__ float sl[32];
    if (j == 0) sl[p] = acc * 0.05103103630798288f;
    __syncthreads();
    if (tid < 32) {
        float logit = sl[tid];
        float mx = logit;
#pragma unroll
        for (int o = 4; o; o >>= 1) mx = fmaxf(mx, __shfl_xor_sync(0xffffffffu, mx, o));
        float e = __expf(logit - mx);
        float s = e;
#pragma unroll
        for (int o = 4; o; o >>= 1) s += __shfl_xor_sync(0xffffffffu, s, o);
        wout[tid] = e / s;
    }
}

// ---------------- hard-concrete via HW tanh: z = clamp(0.5 + 0.6*tanh(0.75*t)) ----------------
__device__ __forceinline__ float hc_z(float u, float la)
{
    u = fminf(fmaxf(u, 1e-6f), 1.0f - 1e-6f);
    float t = (__logf(u) - __logf(1.0f - u) + la) * 0.75f;
    float z = fmaf(0.6f, tanh_fast(t), 0.5f);
    return fminf(fmaxf(z, 0.0f), 1.0f);
}

// ---------------- fused delta: hard-concrete + contraction (HBM-bound bulk) ----------------
__global__ void __launch_bounds__(256) delta_kernel(
    const float* __restrict__ u_a, const float* __restrict__ la_a, const float* __restrict__ phi_a,
    const float* __restrict__ u_b, const float* __restrict__ la_b, const float* __restrict__ phi_b,
    const float* __restrict__ wbuf, float* __restrict__ out)
{
    __shared__ float ws[32];
    if (threadIdx.x < 32) ws[threadIdx.x] = wbuf[threadIdx.x];
    __syncthreads();

    int g = blockIdx.x * 256 + threadIdx.x;
    bool isB = g >= GCNT;
    int gg = isB ? g - GCNT : g;
    const float* up = isB ? u_b : u_a;
    const float* lp = isB ? la_b : la_a;
    const float* pp = isB ? phi_b : phi_a;

    size_t e8 = (size_t)gg * 8;
    float4 u0 = __ldcs((const float4*)(up + e8));
    float4 u1 = __ldcs((const float4*)(up + e8 + 4));
    float4 l0 = __ldcs((const float4*)(lp + e8));
    float4 l1 = __ldcs((const float4*)(lp + e8 + 4));
    float phi = __ldcs(pp + gg);

    float z[8];
    z[0] = hc_z(u0.x, l0.x); z[1] = hc_z(u0.y, l0.y);
    z[2] = hc_z(u0.z, l0.z); z[3] = hc_z(u0.w, l0.w);
    z[4] = hc_z(u1.x, l1.x); z[5] = hc_z(u1.y, l1.y);
    z[6] = hc_z(u1.z, l1.z); z[7] = hc_z(u1.w, l1.w);

    size_t base = (size_t)(isB ? GCNT : 0) + (size_t)gg;
#pragma unroll
    for (int b = 0; b < 4; b++) {
        float acc = 0.f;
#pragma unroll
        for (int m = 0; m < 8; m++) acc = fmaf(z[m], ws[b * 8 + m], acc);
        __stcs(out + (size_t)b * OUTROW + base, acc * phi);
    }
}

// ---------------- host launch ----------------
extern "C" void kernel_launch(void* const* d_in, const int* in_sizes, int n_in,
                              void* d_out, int out_size)
{
    const float* x      = (const float*)d_in[0];
    const float* u_a    = (const float*)d_in[1];
    const float* u_b    = (const float*)d_in[2];
    const float* phi_a  = (const float*)d_in[3];
    const float* phi_b  = (const float*)d_in[4];
    const float* la_a   = (const float*)d_in[5];
    const float* la_b   = (const float*)d_in[6];
    const float* Wp     = (const float*)d_in[7];
    const float* bp     = (const float*)d_in[8];
    const float* skills = (const float*)d_in[9];
    const float* cenc   = (const float*)d_in[10];
    const float* ln1_g  = (const float*)d_in[11];
    const float* ln1_b  = (const float*)d_in[12];
    const float* Wqkv   = (const float*)d_in[13];
    const float* bqkv   = (const float*)d_in[14];
    const float* Wo     = (const float*)d_in[15];
    const float* bo     = (const float*)d_in[16];
    const float* ln2_g  = (const float*)d_in[17];
    const float* ln2_b  = (const float*)d_in[18];
    const float* W1     = (const float*)d_in[19];
    const float* b1     = (const float*)d_in[20];
    const float* W2     = (const float*)d_in[21];
    const float* b2     = (const float*)d_in[22];
    const float* mk     = (const float*)d_in[23];
    float* out = (float*)d_out;

    float* scratch = nullptr;
    cudaGetSymbolAddress((void**)&scratch, g_scratch);
    float* tok  = scratch + OFF_TOK;
    float* ybuf = scratch + OFF_Y;
    float* qb   = scratch + OFF_Q;
    float* sc   = scratch + OFF_SC;
    float* ob   = scratch + OFF_O;
    float* ff   = scratch + OFF_FF;
    float* wbuf = scratch + OFF_W;
    float* kT   = scratch + OFF_KT;
    float* vb   = scratch + OFF_V;

    // 1. h = x@Wp + bp + count_enc  -> tok rows [4:260)
    gemm_kernel<<<dim3(DD / 64, NN / 64, BB), 256>>>(
        x, Wp, bp, cenc, tok + 4 * DD,
        NN, DD, DD,
        (long long)NN * DD, 0LL, (long long)TT * DD, 0LL, 1,
        DD, 1.0f, 2);

    // 2. skill tokens
    fill_skills_kernel<<<(BB * 4 * DD + 255) / 256, 256>>>(skills, tok);

    // 3. LN1
    ln_kernel<<<ROWS, 128>>>(tok, ln1_g, ln1_b, ybuf);

    // 4. qkv = y @ Wqkv + bqkv, scattered to q / kT / v
    gemm_kernel<<<dim3(3 * DD / 64, (ROWS + 63) / 64, 1), 256>>>(
        ybuf, Wqkv, bqkv, nullptr, qb,
        ROWS, 3 * DD, DD,
        0LL, 0LL, 0LL, 0LL, 1,
        0, 1.0f, 4);

    // 5. scores = q @ kT / sqrt(96)
    gemm_kernel<<<dim3((TT + 63) / 64, (TT + 63) / 64, BB * HH), 256>>>(
        qb, kT, nullptr, nullptr, sc,
        TT, TT, DH,
        (long long)TT * DH, (long long)TT * DH, (long long)TT * TT, 0LL, 1,
        TT, 0.10206207261596577f, 0);

    // 6. softmax
    softmax260_kernel<<<BB * HH * TT, 128>>>(sc);

    // 7. o = att @ v -> (B,T,D)
    gemm_kernel<<<dim3((DH + 63) / 64, (TT + 63) / 64, BB * HH), 256>>>(
        sc, vb, nullptr, nullptr, ob,
        TT, DH, TT,
        (long long)TT * TT, (long long)TT * DH,
        (long long)TT * DD, (long long)DH, HH,
        DD, 1.0f, 0);

    // 8. tok += o @ Wo + bo
    gemm_kernel<<<dim3(DD / 64, (ROWS + 63) / 64, 1), 256>>>(
        ob, Wo, bo, tok, tok,
        ROWS, DD, DD,
        0LL, 0LL, 0LL, 0LL, 1,
        DD, 1.0f, 3);

    // 9. LN2
    ln_kernel<<<ROWS, 128>>>(tok, ln2_g, ln2_b, ybuf);

    // 10. ff = gelu(y @ W1 + b1)
    gemm_kernel<<<dim3(2 * DD / 64, (ROWS + 63) / 64, 1), 256>>>(
        ybuf, W1, b1, nullptr, ff,
        ROWS, 2 * DD, DD,
        0LL, 0LL, 0LL, 0LL, 1,
        2 * DD, 1.0f, 1);

    // 11. tok += ff @ W2 + b2
    gemm_kernel<<<dim3(DD / 64, (ROWS + 63) / 64, 1), 256>>>(
        ff, W2, b2, tok, tok,
        ROWS, DD, 2 * DD,
        0LL, 0LL, 0LL, 0LL, 1,
        DD, 1.0f, 3);

    // 12. w
    compute_w_kernel<<<1, 256>>>(tok, mk, wbuf);

    // 13. fused hard-concrete + contraction
    delta_kernel<<<(2 * GCNT) / 256, 256>>>(
        u_a, la_a, phi_a, u_b, la_b, phi_b, wbuf, out);
}

// round 9
// speedup vs baseline: 1.8352x; 1.3175x over previous
#include <cuda_runtime.h>
#include <cuda_fp16.h>
#include <cstdint>
#include <math.h>

// ---------------- problem constants ----------------
#define BB   4
#define NN   256
#define DD   384
#define LL   12
#define F1C  1536
#define F2C  384
#define MM   8
#define HH   4
#define TT   260          // 4 skill tokens + 256
#define DH   96           // D / H
#define ROWS (BB*TT)      // 1040
#define TTP  272          // TT padded to multiple of 16

#define GCNT   (LL*F1C*F2C)          // 7,077,888 groups per side
#define OUTROW (2LL*GCNT)

// ---------------- fp32 scratch ----------------
#define OFF_TOK  0
#define SZ_TOK   (ROWS*DD)
#define OFF_SC   (OFF_TOK + SZ_TOK)
#define SZ_SC    (BB*HH*TT*TT)
#define OFF_O    (OFF_SC + SZ_SC)
#define SZ_O     (ROWS*DD)
#define OFF_W    (OFF_O + SZ_O)
#define SZ_W     32
#define SCRATCH_TOTAL (OFF_W + SZ_W)
__device__ float g_scratch[SCRATCH_TOTAL];

// ---------------- fp16 scratch (offsets in halves) ----------------
#define HX_OFF     0
#define HWP_OFF    393216
#define HWQKV_OFF  540672
#define HWO_OFF    983040
#define HW1_OFF    1130496
#define HW2_OFF    1425408
#define HQ_OFF     1720320
#define HKT_OFF    2119680
#define HV_OFF     2537472
#define HPR_OFF    2955264
#define HY_OFF     4086784
#define HOB_OFF    4486144
#define HFF_OFF    4885504
#define HTOTAL     5684224
__device__ __half g_half[HTOTAL];

__device__ __forceinline__ float tanh_fast(float x)
{
    float r;
    asm("tanh.approx.f32 %0, %1;" : "=f"(r) : "f"(x));
    return r;
}

// ---------------- fp32 -> fp16 conversion of x + weights ----------------
__global__ void conv_kernel(const float* __restrict__ x,  const float* __restrict__ Wp,
                            const float* __restrict__ Wqkv, const float* __restrict__ Wo,
                            const float* __restrict__ W1, const float* __restrict__ W2)
{
    int i = blockIdx.x * 256 + threadIdx.x;      // total 1720320
    if (i >= 1720320) return;
    float v;
    if      (i < 393216)  v = x[i];
    else if (i < 540672)  v = Wp[i - 393216];
    else if (i < 983040)  v = Wqkv[i - 540672];
    else if (i < 1130496) v = Wo[i - 983040];
    else if (i < 1425408) v = W1[i - 1130496];
    else                  v = W2[i - 1425408];
    g_half[i] = __float2half_rn(v);
}

// ---------------- epilogue helper: one float2 of output ----------------
// epi: 0=none, 1=gelu->half only, 2=+R[col], 3=+Rm residual, 4=qkv scatter
__device__ __forceinline__ void epi_store2(
    float v0, float v1, int row, int col, int Mr, int N,
    const float* bias, const float* R, const float* Rm,
    float* C, __half* hC, int ldc, float scale, int epi)
{
    if (row >= Mr || col >= N) return;
    float b0 = 0.f, b1 = 0.f;
    if (bias) { b0 = bias[col]; b1 = bias[col + 1]; }
    v0 = v0 * scale + b0;
    v1 = v1 * scale + b1;
    if (epi == 1) {
        float t;
        t = v0; v0 = 0.5f * t * (1.f + tanh_fast(0.7978845608028654f * (t + 0.044715f * t * t * t)));
        t = v1; v1 = 0.5f * t * (1.f + tanh_fast(0.7978845608028654f * (t + 0.044715f * t * t * t)));
    } else if (epi == 2) {
        v0 += R[col]; v1 += R[col + 1];
    } else if (epi == 3) {
        const float* rr = Rm + (size_t)row * ldc + col;
        v0 += rr[0]; v1 += rr[1];
    }
    if (epi == 4) {
        int b = row / TT, t = row - b * TT;
        int s = col / DD;
        int rem = col - s * DD;
        int h = rem / DH;
        int d = rem - h * DH;
        int bh = b * HH + h;
        if (s == 0) {
            *(__half2*)(g_half + HQ_OFF + ((size_t)(bh * TT + t)) * DH + d) =
                __floats2half2_rn(v0, v1);
        } else if (s == 1) {
            g_half[HKT_OFF + ((size_t)(bh * DH + d)) * TTP + t]     = __float2half_rn(v0);
            g_half[HKT_OFF + ((size_t)(bh * DH + d + 1)) * TTP + t] = __float2half_rn(v1);
        } else {
            *(__half2*)(g_half + HV_OFF + ((size_t)(bh * TTP + t)) * DH + d) =
                __floats2half2_rn(v0, v1);
        }
        return;
    }
    if (C)  *(float2*)(C + (size_t)row * ldc + col) = make_float2(v0, v1);
    if (hC) *(__half2*)(hC + (size_t)row * ldc + col) = __floats2half2_rn(v0, v1);
}

// ---------------- fp16 tensor-core GEMM: CTA 128x64, warp 32x32, mma m16n8k16 ----------------
__global__ void __launch_bounds__(256) hgemm_kernel(
    const __half* __restrict__ A, const __half* __restrict__ B,
    const float* __restrict__ bias, const float* __restrict__ R,
    float* __restrict__ C, __half* __restrict__ hC,
    int Mr, int N, int K, int lda, int ldb, int Nload,
    long long aBS, long long wBS, long long cBS1, long long cBS2, int cdiv,
    int ldc, float scale, int epi)
{
    int z = blockIdx.z;
    A += (size_t)z * aBS;
    B += (size_t)z * wBS;
    size_t coff = (size_t)(z / cdiv) * cBS1 + (size_t)(z % cdiv) * cBS2;
    if (C)  C += coff;
    if (hC) hC += coff;
    const float* Rm = (epi == 3) ? (R + coff) : nullptr;

    __shared__ __half As[2][128][24];   // 16 halves padded to 24 (48B rows)
    __shared__ __half Bs[2][16][72];    // 64 halves padded to 72 (144B rows)

    int bm = blockIdx.y * 128, bn = blockIdx.x * 64;
    int tid = threadIdx.x;
    int lane = tid & 31, warp = tid >> 5;
    int wm = warp >> 1, wn = warp & 1;  // 4x2 warp grid, each 32x32

    int ar = tid >> 1;                  // 0..127
    int ac = (tid & 1) << 3;            // 0 or 8
    int arow = bm + ar;
    bool a_ok = arow < Mr;
    const __half* Ap = A + (size_t)(a_ok ? arow : 0) * lda + ac;

    int br = tid >> 3;                  // used for tid<128 -> 0..15
    int bc = (tid & 7) << 3;
    bool b_ok = (tid < 128) && ((bn + bc) < Nload);
    const __half* Bp = B + (size_t)br * ldb + bn + bc;

    float acc[2][4][4];
#pragma unroll
    for (int mt = 0; mt < 2; mt++)
#pragma unroll
        for (int nt = 0; nt < 4; nt++)
#pragma unroll
            for (int i = 0; i < 4; i++) acc[mt][nt][i] = 0.f;

    {
        uint4 aval = make_uint4(0, 0, 0, 0), bval = make_uint4(0, 0, 0, 0);
        if (a_ok) aval = *(const uint4*)(Ap);
        if (b_ok) bval = *(const uint4*)(Bp);
        *(uint4*)&As[0][ar][ac] = aval;
        if (tid < 128) *(uint4*)&Bs[0][br][bc] = bval;
    }
    __syncthreads();

    int lb = lane >> 3, lr = lane & 7;
    int frag_row = (lb & 1) * 8 + lr;   // 0..15
    int frag_col = (lb >> 1) * 8;       // 0 or 8

    int cur = 0;
    for (int k0 = 0; k0 < K; k0 += 16) {
        int kn = k0 + 16;
        uint4 aval = make_uint4(0, 0, 0, 0), bval = make_uint4(0, 0, 0, 0);
        if (kn < K) {
            if (a_ok) aval = *(const uint4*)(Ap + kn);
            if (b_ok) bval = *(const uint4*)(Bp + (size_t)kn * ldb);
        }

        unsigned int afr[2][4];
        unsigned int bfr[4][2];
#pragma unroll
        for (int mt = 0; mt < 2; mt++) {
            unsigned int addr = (unsigned int)__cvta_generic_to_shared(
                &As[cur][wm * 32 + mt * 16 + frag_row][frag_col]);
            asm volatile("ldmatrix.sync.aligned.m8n8.x4.shared.b16 {%0,%1,%2,%3}, [%4];"
                : "=r"(afr[mt][0]), "=r"(afr[mt][1]), "=r"(afr[mt][2]), "=r"(afr[mt][3])
                : "r"(addr));
        }
#pragma unroll
        for (int p = 0; p < 2; p++) {
            unsigned int addr = (unsigned int)__cvta_generic_to_shared(
                &Bs[cur][frag_row][wn * 32 + p * 16 + frag_col]);
            asm volatile("ldmatrix.sync.aligned.m8n8.x4.trans.shared.b16 {%0,%1,%2,%3}, [%4];"
                : "=r"(bfr[p * 2][0]), "=r"(bfr[p * 2][1]),
                  "=r"(bfr[p * 2 + 1][0]), "=r"(bfr[p * 2 + 1][1])
                : "r"(addr));
        }
#pragma unroll
        for (int mt = 0; mt < 2; mt++)
#pragma unroll
            for (int nt = 0; nt < 4; nt++) {
                asm volatile(
                    "mma.sync.aligned.m16n8k16.row.col.f32.f16.f16.f32 "
                    "{%0,%1,%2,%3}, {%4,%5,%6,%7}, {%8,%9}, {%0,%1,%2,%3};"
                    : "+f"(acc[mt][nt][0]), "+f"(acc[mt][nt][1]),
                      "+f"(acc[mt][nt][2]), "+f"(acc[mt][nt][3])
                    : "r"(afr[mt][0]), "r"(afr[mt][1]), "r"(afr[mt][2]), "r"(afr[mt][3]),
                      "r"(bfr[nt][0]), "r"(bfr[nt][1]));
            }

        if (kn < K) {
            int nxt = cur ^ 1;
            *(uint4*)&As[nxt][ar][ac] = aval;
            if (tid < 128) *(uint4*)&Bs[nxt][br][bc] = bval;
        }
        __syncthreads();
        cur ^= 1;
    }

    // epilogue
    int g = lane >> 2, t2 = (lane & 3) << 1;
#pragma unroll
    for (int mt = 0; mt < 2; mt++) {
        int row0 = bm + wm * 32 + mt * 16 + g;
#pragma unroll
        for (int nt = 0; nt < 4; nt++) {
            int col = bn + wn * 32 + nt * 8 + t2;
            epi_store2(acc[mt][nt][0], acc[mt][nt][1], row0,     col, Mr, N,
                       bias, R, Rm, C, hC, ldc, scale, epi);
            epi_store2(acc[mt][nt][2], acc[mt][nt][3], row0 + 8, col, Mr, N,
                       bias, R, Rm, C, hC, ldc, scale, epi);
        }
    }
}

// ---------------- fill skill tokens ----------------
__global__ void fill_skills_kernel(const float* __restrict__ skills, float* __restrict__ tok)
{
    int i = blockIdx.x * 256 + threadIdx.x;
    if (i >= BB * 4 * DD) return;
    int b = i / (4 * DD);
    int r = i % (4 * DD);
    tok[(size_t)(b * TT) * DD + r] = skills[r];
}

// ---------------- layernorm: fp32 in -> half out ----------------
__global__ void __launch_bounds__(128) ln_kernel(
    const float* __restrict__ X, const float* __restrict__ gw,
    const float* __restrict__ bw, __half* __restrict__ Y)
{
    int row = blockIdx.x;
    int tid = threadIdx.x;
    const float* x = X + (size_t)row * DD;
    float v0 = x[tid], v1 = x[tid + 128], v2 = x[tid + 256];
    float s = v0 + v1 + v2;
    float q = v0 * v0 + v1 * v1 + v2 * v2;
#pragma unroll
    for (int o = 16; o; o >>= 1) {
        s += __shfl_xor_sync(0xffffffffu, s, o);
        q += __shfl_xor_sync(0xffffffffu, q, o);
    }
    __shared__ float ss[4], qq[4];
    if ((tid & 31) == 0) { ss[tid >> 5] = s; qq[tid >> 5] = q; }
    __syncthreads();
    s = ss[0] + ss[1] + ss[2] + ss[3];
    q = qq[0] + qq[1] + qq[2] + qq[3];
    float mean = s * (1.f / DD);
    float var = q * (1.f / DD) - mean * mean;
    float inv = rsqrtf(var + 1e-6f);
    __half* y = Y + (size_t)row * DD;
    y[tid]       = __float2half_rn((v0 - mean) * inv * gw[tid]       + bw[tid]);
    y[tid + 128] = __float2half_rn((v1 - mean) * inv * gw[tid + 128] + bw[tid + 128]);
    y[tid + 256] = __float2half_rn((v2 - mean) * inv * gw[tid + 256] + bw[tid + 256]);
}

// ---------------- softmax over 260 cols: fp32 scores -> half probs (stride 272) ----------------
__global__ void __launch_bounds__(128) softmax260_kernel(
    const float* __restrict__ S, __half* __restrict__ P)
{
    int row = blockIdx.x;
    const float* p = S + (size_t)row * TT;
    __half* ph = P + (size_t)row * TTP;
    int tid = threadIdx.x;
    float v0 = p[tid], v1 = p[tid + 128];
    float v2 = (tid < 4) ? p[tid + 256] : -1e30f;
    float mx = fmaxf(fmaxf(v0, v1), v2);
#pragma unroll
    for (int o = 16; o; o >>= 1) mx = fmaxf(mx, __shfl_xor_sync(0xffffffffu, mx, o));
    __shared__ float sm[4];
    if ((tid & 31) == 0) sm[tid >> 5] = mx;
    __syncthreads();
    mx = fmaxf(fmaxf(sm[0], sm[1]), fmaxf(sm[2], sm[3]));
    float e0 = __expf(v0 - mx), e1 = __expf(v1 - mx);
    float e2 = (tid < 4) ? __expf(v2 - mx) : 0.f;
    float s = e0 + e1 + e2;
#pragma unroll
    for (int o = 16; o; o >>= 1) s += __shfl_xor_sync(0xffffffffu, s, o);
    __shared__ float sq[4];
    if ((tid & 31) == 0) sq[tid >> 5] = s;
    __syncthreads();
    s = sq[0] + sq[1] + sq[2] + sq[3];
    float inv = __fdividef(1.f, s);
    ph[tid]       = __float2half_rn(e0 * inv);
    ph[tid + 128] = __float2half_rn(e1 * inv);
    if (tid < 4)  ph[tid + 256] = __float2half_rn(e2 * inv);
    if (tid >= 4 && tid < 16) ph[tid + 256] = __float2half_rn(0.f);
}

// ---------------- w = softmax(mean(tok[:, :4]) @ mk^T / sqrt(D)) ----------------
__global__ void __launch_bounds__(256) compute_w_kernel(
    const float* __restrict__ tok, const float* __restrict__ mk,
    float* __restrict__ wout)
{
    int tid = threadIdx.x;
    int p = tid >> 3;
    int b = p >> 3, m = p & 7;
    int j = tid & 7;
    const float* tb = tok + (size_t)b * TT * DD;
    const float* key = mk + (size_t)m * DD;
    float acc = 0.f;
    for (int d = j * 4; d < DD; d += 32) {
        float4 k4 = *(const float4*)(key + d);
        float4 t0 = *(const float4*)(tb + d);
        float4 t1 = *(const float4*)(tb + DD + d);
        float4 t2 = *(const float4*)(tb + 2 * DD + d);
        float4 t3 = *(const float4*)(tb + 3 * DD + d);
        acc = fmaf(0.25f * (t0.x + t1.x + t2.x + t3.x), k4.x, acc);
        acc = fmaf(0.25f * (t0.y + t1.y + t2.y + t3.y), k4.y, acc);
        acc = fmaf(0.25f * (t0.z + t1.z + t2.z + t3.z), k4.z, acc);
        acc = fmaf(0.25f * (t0.w + t1.w + t2.w + t3.w), k4.w, acc);
    }
    acc += __shfl_xor_sync(0xffffffffu, acc, 4);
    acc += __shfl_xor_sync(0xffffffffu, acc, 2);
    acc += __shfl_xor_sync(0xffffffffu, acc, 1);
    __shared__ float sl[32];
    if (j == 0) sl[p] = acc * 0.05103103630798288f;
    __syncthreads();
    if (tid < 32) {
        float logit = sl[tid];
        float mx = logit;
#pragma unroll
        for (int o = 4; o; o >>= 1) mx = fmaxf(mx, __shfl_xor_sync(0xffffffffu, mx, o));
        float e = __expf(logit - mx);
        float s = e;
#pragma unroll
        for (int o = 4; o; o >>= 1) s += __shfl_xor_sync(0xffffffffu, s, o);
        wout[tid] = e / s;
    }
}

// ---------------- hard-concrete via HW tanh ----------------
__device__ __forceinline__ float hc_z(float u, float la)
{
    u = fminf(fmaxf(u, 1e-6f), 1.0f - 1e-6f);
    float t = (__logf(u) - __logf(1.0f - u) + la) * 0.75f;
    float z = fmaf(0.6f, tanh_fast(t), 0.5f);
    return fminf(fmaxf(z, 0.0f), 1.0f);
}

// ---------------- fused delta: hard-concrete + contraction ----------------
__global__ void __launch_bounds__(256) delta_kernel(
    const float* __restrict__ u_a, const float* __restrict__ la_a, const float* __restrict__ phi_a,
    const float* __restrict__ u_b, const float* __restrict__ la_b, const float* __restrict__ phi_b,
    const float* __restrict__ wbuf, float* __restrict__ out)
{
    __shared__ float ws[32];
    if (threadIdx.x < 32) ws[threadIdx.x] = wbuf[threadIdx.x];
    __syncthreads();

    int g = blockIdx.x * 256 + threadIdx.x;
    bool isB = g >= GCNT;
    int gg = isB ? g - GCNT : g;
    const float* up = isB ? u_b : u_a;
    const float* lp = isB ? la_b : la_a;
    const float* pp = isB ? phi_b : phi_a;

    size_t e8 = (size_t)gg * 8;
    float4 u0 = __ldcs((const float4*)(up + e8));
    float4 u1 = __ldcs((const float4*)(up + e8 + 4));
    float4 l0 = __ldcs((const float4*)(lp + e8));
    float4 l1 = __ldcs((const float4*)(lp + e8 + 4));
    float phi = __ldcs(pp + gg);

    float z[8];
    z[0] = hc_z(u0.x, l0.x); z[1] = hc_z(u0.y, l0.y);
    z[2] = hc_z(u0.z, l0.z); z[3] = hc_z(u0.w, l0.w);
    z[4] = hc_z(u1.x, l1.x); z[5] = hc_z(u1.y, l1.y);
    z[6] = hc_z(u1.z, l1.z); z[7] = hc_z(u1.w, l1.w);

    size_t base = (size_t)(isB ? GCNT : 0) + (size_t)gg;
#pragma unroll
    for (int b = 0; b < 4; b++) {
        float acc = 0.f;
#pragma unroll
        for (int m = 0; m < 8; m++) acc = fmaf(z[m], ws[b * 8 + m], acc);
        __stcs(out + (size_t)b * OUTROW + base, acc * phi);
    }
}

// ---------------- host launch ----------------
extern "C" void kernel_launch(void* const* d_in, const int* in_sizes, int n_in,
                              void* d_out, int out_size)
{
    const float* x      = (const float*)d_in[0];
    const float* u_a    = (const float*)d_in[1];
    const float* u_b    = (const float*)d_in[2];
    const float* phi_a  = (const float*)d_in[3];
    const float* phi_b  = (const float*)d_in[4];
    const float* la_a   = (const float*)d_in[5];
    const float* la_b   = (const float*)d_in[6];
    const float* Wp     = (const float*)d_in[7];
    const float* bp     = (const float*)d_in[8];
    const float* skills = (const float*)d_in[9];
    const float* cenc   = (const float*)d_in[10];
    const float* ln1_g  = (const float*)d_in[11];
    const float* ln1_b  = (const float*)d_in[12];
    const float* Wqkv   = (const float*)d_in[13];
    const float* bqkv   = (const float*)d_in[14];
    const float* Wo     = (const float*)d_in[15];
    const float* bo     = (const float*)d_in[16];
    const float* ln2_g  = (const float*)d_in[17];
    const float* ln2_b  = (const float*)d_in[18];
    const float* W1     = (const float*)d_in[19];
    const float* b1     = (const float*)d_in[20];
    const float* W2     = (const float*)d_in[21];
    const float* b2     = (const float*)d_in[22];
    const float* mk     = (const float*)d_in[23];
    float* out = (float*)d_out;

    float* scratch = nullptr;
    cudaGetSymbolAddress((void**)&scratch, g_scratch);
    __half* hbuf = nullptr;
    cudaGetSymbolAddress((void**)&hbuf, g_half);

    float* tok  = scratch + OFF_TOK;
    float* sc   = scratch + OFF_SC;
    float* ob   = scratch + OFF_O;
    float* wbuf = scratch + OFF_W;

    const __half* hx    = hbuf + HX_OFF;
    const __half* hWp   = hbuf + HWP_OFF;
    const __half* hWqkv = hbuf + HWQKV_OFF;
    const __half* hWo   = hbuf + HWO_OFF;
    const __half* hW1   = hbuf + HW1_OFF;
    const __half* hW2   = hbuf + HW2_OFF;
    const __half* hq    = hbuf + HQ_OFF;
    const __half* hkT   = hbuf + HKT_OFF;
    const __half* hv    = hbuf + HV_OFF;
    const __half* hpr   = hbuf + HPR_OFF;
    __half* hy  = hbuf + HY_OFF;
    __half* hob = hbuf + HOB_OFF;
    __half* hff = hbuf + HFF_OFF;

    // 0. convert x + weights to fp16
    conv_kernel<<<(1720320 + 255) / 256, 256>>>(x, Wp, Wqkv, Wo, W1, W2);

    // 1. h = x@Wp + bp + count_enc -> tok rows [4:260)
    hgemm_kernel<<<dim3(DD / 64, 2, BB), 256>>>(
        hx, hWp, bp, cenc, tok + 4 * DD, nullptr,
        NN, DD, DD, DD, DD, DD,
        (long long)NN * DD, 0LL, (long long)TT * DD, 0LL, 1,
        DD, 1.0f, 2);

    // 2. skill tokens
    fill_skills_kernel<<<(BB * 4 * DD + 255) / 256, 256>>>(skills, tok);

    // 3. LN1 -> half y
    ln_kernel<<<ROWS, 128>>>(tok, ln1_g, ln1_b, hy);

    // 4. qkv = y @ Wqkv + bqkv -> scattered half q / kT / v
    hgemm_kernel<<<dim3(3 * DD / 64, (ROWS + 127) / 128, 1), 256>>>(
        hy, hWqkv, bqkv, nullptr, nullptr, nullptr,
        ROWS, 3 * DD, DD, DD, 3 * DD, 3 * DD,
        0LL, 0LL, 0LL, 0LL, 1,
        0, 1.0f, 4);

    // 5. scores = q @ kT / sqrt(96)  (batched over BH=16)
    hgemm_kernel<<<dim3((TT + 63) / 64, (TT + 127) / 128, BB * HH), 256>>>(
        hq, hkT, nullptr, nullptr, sc, nullptr,
        TT, TT, DH, DH, TTP, TTP,
        (long long)TT * DH, (long long)DH * TTP, (long long)TT * TT, 0LL, 1,
        TT, 0.10206207261596577f, 0);

    // 6. softmax -> half probs (stride 272, zero tail)
    softmax260_kernel<<<BB * HH * TT, 128>>>(sc, hbuf + HPR_OFF);

    // 7. o = probs @ v -> fp32 ob (B,T,D) + half mirror
    hgemm_kernel<<<dim3((DH + 63) / 64, (TT + 127) / 128, BB * HH), 256>>>(
        hpr, hv, nullptr, nullptr, ob, hob,
        TT, DH, TTP, TTP, DH, DH,
        (long long)TT * TTP, (long long)TTP * DH,
        (long long)TT * DD, (long long)DH, HH,
        DD, 1.0f, 0);

    // 8. tok += o @ Wo + bo
    hgemm_kernel<<<dim3(DD / 64, (ROWS + 127) / 128, 1), 256>>>(
        hob, hWo, bo, tok, tok, nullptr,
        ROWS, DD, DD, DD, DD, DD,
        0LL, 0LL, 0LL, 0LL, 1,
        DD, 1.0f, 3);

    // 9. LN2 -> half y
    ln_kernel<<<ROWS, 128>>>(tok, ln2_g, ln2_b, hy);

    // 10. ff = gelu(y @ W1 + b1) -> half only
    hgemm_kernel<<<dim3(2 * DD / 64, (ROWS + 127) / 128, 1), 256>>>(
        hy, hW1, b1, nullptr, nullptr, hff,
        ROWS, 2 * DD, DD, DD, 2 * DD, 2 * DD,
        0LL, 0LL, 0LL, 0LL, 1,
        2 * DD, 1.0f, 1);

    // 11. tok += ff @ W2 + b2
    hgemm_kernel<<<dim3(DD / 64, (ROWS + 127) / 128, 1), 256>>>(
        hff, hW2, b2, tok, tok, nullptr,
        ROWS, DD, 2 * DD, 2 * DD, DD, DD,
        0LL, 0LL, 0LL, 0LL, 1,
        DD, 1.0f, 3);

    // 12. w
    compute_w_kernel<<<1, 256>>>(tok, mk, wbuf);

    // 13. fused hard-concrete + contraction
    delta_kernel<<<(2 * GCNT) / 256, 256>>>(
        u_a, la_a, phi_a, u_b, la_b, phi_b, wbuf, out);
}